// round 1
// baseline (speedup 1.0000x reference)
#include <cuda_runtime.h>
#include <cuda_bf16.h>
#include <math.h>

// Problem constants
#define IMGS 48
#define H 512
#define W 512
#define IMG_ELEMS (H * W)            // 262144
#define VALID 506                    // 512 - 7 + 1
#define N_TOTAL (48.0 * 512.0 * 512.0)
#define N_SSIM  (48.0 * 506.0 * 506.0)

// Global accumulators (device scratch — no allocations allowed)
__device__ double g_sum_abs;
__device__ double g_sum_sq;
__device__ double g_sum_S;
__device__ unsigned g_minkey[IMGS];
__device__ unsigned g_maxkey[IMGS];

// Order-preserving float <-> uint key for atomicMin/Max
__device__ __forceinline__ unsigned fkey(float f) {
    unsigned u = __float_as_uint(f);
    return (u & 0x80000000u) ? ~u : (u | 0x80000000u);
}
__device__ __forceinline__ float funkey(unsigned k) {
    unsigned u = (k & 0x80000000u) ? (k & 0x7FFFFFFFu) : ~k;
    return __uint_as_float(u);
}

// ---------------------------------------------------------------------------
// Kernel 0: zero accumulators, init min/max keys
// ---------------------------------------------------------------------------
__global__ void k_init() {
    int t = threadIdx.x;
    if (t == 0) { g_sum_abs = 0.0; g_sum_sq = 0.0; g_sum_S = 0.0; }
    if (t < IMGS) { g_minkey[t] = 0xFFFFFFFFu; g_maxkey[t] = 0u; }
}

// ---------------------------------------------------------------------------
// Kernel 1: MAE/MSE sums + per-image min/max of y_true*mask.
// 32 blocks per image x 256 threads, 8 float4 per thread (8192 elems/block).
// ---------------------------------------------------------------------------
__global__ void __launch_bounds__(256) k_stats(
    const float4* __restrict__ p4, const float4* __restrict__ t4,
    const float4* __restrict__ m4)
{
    int img = blockIdx.x >> 5;   // 32 blocks / image
    int blk = blockIdx.x & 31;
    long base = (long)img * (IMG_ELEMS / 4) + (long)blk * 2048;

    float sa = 0.f, sq = 0.f;
    float mn = INFINITY, mx = -INFINITY;

#pragma unroll
    for (int i = 0; i < 8; i++) {
        long idx = base + threadIdx.x + i * 256;
        float4 p = p4[idx];
        float4 t = t4[idx];
        float4 m = m4[idx];
        float y0 = t.x * m.x, y1 = t.y * m.y, y2 = t.z * m.z, y3 = t.w * m.w;
        float d0 = p.x * m.x - y0;
        float d1 = p.y * m.y - y1;
        float d2 = p.z * m.z - y2;
        float d3 = p.w * m.w - y3;
        sa += fabsf(d0) + fabsf(d1) + fabsf(d2) + fabsf(d3);
        sq += d0 * d0 + d1 * d1 + d2 * d2 + d3 * d3;
        mn = fminf(mn, fminf(fminf(y0, y1), fminf(y2, y3)));
        mx = fmaxf(mx, fmaxf(fmaxf(y0, y1), fmaxf(y2, y3)));
    }

    // warp reduce
#pragma unroll
    for (int o = 16; o; o >>= 1) {
        sa += __shfl_down_sync(0xffffffffu, sa, o);
        sq += __shfl_down_sync(0xffffffffu, sq, o);
        mn = fminf(mn, __shfl_down_sync(0xffffffffu, mn, o));
        mx = fmaxf(mx, __shfl_down_sync(0xffffffffu, mx, o));
    }
    __shared__ float wsa[8], wsq[8], wmn[8], wmx[8];
    int lane = threadIdx.x & 31, w = threadIdx.x >> 5;
    if (lane == 0) { wsa[w] = sa; wsq[w] = sq; wmn[w] = mn; wmx[w] = mx; }
    __syncthreads();
    if (threadIdx.x == 0) {
        float A = 0.f, Q = 0.f, MN = INFINITY, MX = -INFINITY;
#pragma unroll
        for (int i = 0; i < 8; i++) {
            A += wsa[i]; Q += wsq[i];
            MN = fminf(MN, wmn[i]); MX = fmaxf(MX, wmx[i]);
        }
        atomicAdd(&g_sum_abs, (double)A);
        atomicAdd(&g_sum_sq, (double)Q);
        atomicMin(&g_minkey[img], fkey(MN));
        atomicMax(&g_maxkey[img], fkey(MX));
    }
}

// ---------------------------------------------------------------------------
// Kernel 2: SSIM sum. Block = 32x32 output tile (38x38 input halo).
// Separable 7x7 box filter: horizontal pass into 5 smem planes, vertical pass
// with a 7-deep register circular buffer (sliding window).
// ---------------------------------------------------------------------------
__global__ void __launch_bounds__(256) k_ssim(
    const float* __restrict__ P, const float* __restrict__ T,
    const float* __restrict__ M)
{
    __shared__ float sx[38][40];
    __shared__ float sy[38][40];
    __shared__ float hs[5][38][32];
    __shared__ float sC1, sC2;
    __shared__ float blkred[8];

    int img = blockIdx.z;
    int ox0 = blockIdx.x * 32;
    int oy0 = blockIdx.y * 32;
    int tid = threadIdx.x;

    if (tid == 0) {
        float d = funkey(g_maxkey[img]) - funkey(g_minkey[img]);
        float c1 = 0.01f * d, c2 = 0.03f * d;
        sC1 = c1 * c1;
        sC2 = c2 * c2;
    }

    const float* Pi = P + (size_t)img * IMG_ELEMS;
    const float* Ti = T + (size_t)img * IMG_ELEMS;
    const float* Mi = M + (size_t)img * IMG_ELEMS;

    // Load 38x38 halo (clamped at image edge; clamped values feed only
    // out-of-range outputs which are never accumulated).
    for (int l = tid; l < 38 * 38; l += 256) {
        int r = l / 38, c = l - r * 38;
        int gy = min(oy0 + r, H - 1);
        int gx = min(ox0 + c, W - 1);
        int g = gy * W + gx;
        float m = Mi[g];
        sx[r][c] = Pi[g] * m;
        sy[r][c] = Ti[g] * m;
    }
    __syncthreads();

    // Horizontal 7-tap pass: 38 rows x 32 cols of h-sums for 5 quantities.
    for (int l = tid; l < 38 * 32; l += 256) {
        int r = l >> 5, c = l & 31;
        float s0 = 0.f, s1 = 0.f, s2 = 0.f, s3 = 0.f, s4 = 0.f;
#pragma unroll
        for (int k = 0; k < 7; k++) {
            float x = sx[r][c + k];
            float y = sy[r][c + k];
            s0 += x; s1 += y;
            s2 += x * x; s3 += y * y; s4 += x * y;
        }
        hs[0][r][c] = s0; hs[1][r][c] = s1; hs[2][r][c] = s2;
        hs[3][r][c] = s3; hs[4][r][c] = s4;
    }
    __syncthreads();

    // Vertical pass: thread (tx, ty) handles col tx, rows ty*4 .. ty*4+3.
    int tx = tid & 31;
    int ty = tid >> 5;
    int r0 = ty * 4;

    float buf[5][7];
    float s[5];
#pragma unroll
    for (int q = 0; q < 5; q++) { s[q] = 0.f; buf[q][6] = 0.f; }
#pragma unroll
    for (int j = 0; j < 6; j++) {
#pragma unroll
        for (int q = 0; q < 5; q++) {
            float v = hs[q][r0 + j][tx];
            buf[q][j] = v;
            s[q] += v;
        }
    }

    float C1 = sC1, C2 = sC2;
    const float inv = 1.f / 49.f;
    const float cov = 49.f / 48.f;
    float lsum = 0.f;
    int gx = ox0 + tx;

#pragma unroll
    for (int i = 0; i < 4; i++) {
        int slot = (6 + i) % 7;
#pragma unroll
        for (int q = 0; q < 5; q++) {
            float v = hs[q][r0 + 6 + i][tx];
            s[q] += v - buf[q][slot];
            buf[q][slot] = v;
        }
        int gy = oy0 + r0 + i;
        if (gx < VALID && gy < VALID) {
            float ux = s[0] * inv, uy = s[1] * inv;
            float vx  = cov * (s[2] * inv - ux * ux);
            float vy  = cov * (s[3] * inv - uy * uy);
            float vxy = cov * (s[4] * inv - ux * uy);
            float A1 = 2.f * ux * uy + C1;
            float A2 = 2.f * vxy + C2;
            float B1 = ux * ux + uy * uy + C1;
            float B2 = vx + vy + C2;
            lsum += (A1 * A2) / (B1 * B2);
        }
    }

    // Block reduce S-sum -> one double atomic per block.
#pragma unroll
    for (int o = 16; o; o >>= 1)
        lsum += __shfl_down_sync(0xffffffffu, lsum, o);
    if ((tid & 31) == 0) blkred[ty] = lsum;
    __syncthreads();
    if (tid == 0) {
        float t = 0.f;
#pragma unroll
        for (int i = 0; i < 8; i++) t += blkred[i];
        atomicAdd(&g_sum_S, (double)t);
    }
}

// ---------------------------------------------------------------------------
// Kernel 3: finalize 4 scalar outputs
// ---------------------------------------------------------------------------
__global__ void k_final(float* __restrict__ out) {
    if (threadIdx.x == 0) {
        double mae = g_sum_abs / N_TOTAL;
        double mse = g_sum_sq / N_TOTAL;
        double ssim_loss = 1.0 - g_sum_S / N_SSIM;
        double total = 1.0 * mae + 0.5 * mse + 0.2 * ssim_loss;
        out[0] = (float)total;
        out[1] = (float)mae;
        out[2] = (float)mse;
        out[3] = (float)ssim_loss;
    }
}

// ---------------------------------------------------------------------------
extern "C" void kernel_launch(void* const* d_in, const int* in_sizes, int n_in,
                              void* d_out, int out_size)
{
    const float* y_pred = (const float*)d_in[0];
    const float* y_true = (const float*)d_in[1];
    const float* mask   = (const float*)d_in[2];
    float* out = (float*)d_out;

    k_init<<<1, 64>>>();
    k_stats<<<IMGS * 32, 256>>>((const float4*)y_pred, (const float4*)y_true,
                                (const float4*)mask);
    dim3 grid(16, 16, IMGS);
    k_ssim<<<grid, 256>>>(y_pred, y_true, mask);
    k_final<<<1, 32>>>(out);
}